// round 1
// baseline (speedup 1.0000x reference)
#include <cuda_runtime.h>
#include <math.h>

#define N_WAY     100
#define K_SHOT    10
#define N_SUPPORT 1000
#define N_QUERY   8192
#define F_IN      4096
#define D_EMB     1024
#define EPS_F     1e-6f

// ---------------- scratch (no allocations allowed) ----------------
__device__ float g_Zs[N_SUPPORT * D_EMB];          // support embeddings
__device__ float g_Zq[(size_t)N_QUERY * D_EMB];    // query embeddings (32 MB)
__device__ float g_proto[128 * D_EMB];             // prototypes, zero-padded to 128 rows
__device__ float g_p2[128];                        // ||p||^2 per class
__device__ float g_ps[128];                        // sum(p) per class
__device__ float g_q2[N_QUERY];                    // ||q||^2 per query
__device__ float g_qs[N_QUERY];                    // sum(q) per query
__device__ int   g_order[N_SUPPORT];               // stable argsort of labels

// =====================================================================
// Kernel 1: C[M,1024] = A[M,4096] @ W[4096,1024] + b   (fp32 SGEMM)
// 128x128x16 tile, 8x8 microtile, 256 threads, double-buffered smem.
// which==0 -> write g_Zs, which==1 -> write g_Zq.
// =====================================================================
#define BM 128
#define BN 128
#define BK 16
#define TM 8
#define TN 8

__global__ __launch_bounds__(256, 2)
void sgemm_bias_kernel(const float* __restrict__ A,
                       const float* __restrict__ B,   // W [4096,1024] row-major
                       const float* __restrict__ bias,
                       int which, int M)
{
    const int N = D_EMB, K = F_IN;
    float* __restrict__ C = (which == 0) ? g_Zs : g_Zq;

    __shared__ float As[2][BK][BM];   // transposed: As[k][m]
    __shared__ float Bs[2][BK][BN];

    const int tid      = threadIdx.x;
    const int blockRow = blockIdx.y * BM;
    const int blockCol = blockIdx.x * BN;

    // A tile loads: 128x16 = 512 float4, 2 per thread
    const int aRow = tid >> 2;            // 0..63
    const int aCol = (tid & 3) << 2;      // 0,4,8,12
    // B tile loads: 16x128 = 512 float4, 2 per thread
    const int bRow = tid >> 5;            // 0..7
    const int bCol = (tid & 31) << 2;     // 0..124

    const int tr = (tid >> 4) * TM;       // row of microtile
    const int tc = (tid & 15) * TN;       // col of microtile

    float acc[TM][TN] = {};
    float4 a0, a1, b0, b1;

    const int nk = K / BK;                // 256

    // ---- prefetch tile 0 ----
    {
        int r0 = blockRow + aRow, r1 = r0 + 64;
        a0 = (r0 < M) ? *(const float4*)(A + (size_t)r0 * K + aCol) : make_float4(0.f,0.f,0.f,0.f);
        a1 = (r1 < M) ? *(const float4*)(A + (size_t)r1 * K + aCol) : make_float4(0.f,0.f,0.f,0.f);
        b0 = *(const float4*)(B + (size_t)bRow * N + blockCol + bCol);
        b1 = *(const float4*)(B + (size_t)(bRow + 8) * N + blockCol + bCol);
        As[0][aCol+0][aRow] = a0.x; As[0][aCol+1][aRow] = a0.y;
        As[0][aCol+2][aRow] = a0.z; As[0][aCol+3][aRow] = a0.w;
        As[0][aCol+0][aRow+64] = a1.x; As[0][aCol+1][aRow+64] = a1.y;
        As[0][aCol+2][aRow+64] = a1.z; As[0][aCol+3][aRow+64] = a1.w;
        *(float4*)&Bs[0][bRow][bCol]     = b0;
        *(float4*)&Bs[0][bRow + 8][bCol] = b1;
    }
    __syncthreads();

    for (int kt = 0; kt < nk; kt++) {
        const int cur = kt & 1;
        const int nxt = cur ^ 1;

        if (kt + 1 < nk) {
            const int kc = (kt + 1) * BK;
            int r0 = blockRow + aRow, r1 = r0 + 64;
            a0 = (r0 < M) ? *(const float4*)(A + (size_t)r0 * K + kc + aCol) : make_float4(0.f,0.f,0.f,0.f);
            a1 = (r1 < M) ? *(const float4*)(A + (size_t)r1 * K + kc + aCol) : make_float4(0.f,0.f,0.f,0.f);
            b0 = *(const float4*)(B + (size_t)(kc + bRow) * N + blockCol + bCol);
            b1 = *(const float4*)(B + (size_t)(kc + bRow + 8) * N + blockCol + bCol);
        }

        #pragma unroll
        for (int k = 0; k < BK; k++) {
            float ar[TM], br[TN];
            *(float4*)&ar[0] = *(const float4*)&As[cur][k][tr];
            *(float4*)&ar[4] = *(const float4*)&As[cur][k][tr + 4];
            *(float4*)&br[0] = *(const float4*)&Bs[cur][k][tc];
            *(float4*)&br[4] = *(const float4*)&Bs[cur][k][tc + 4];
            #pragma unroll
            for (int i = 0; i < TM; i++)
                #pragma unroll
                for (int j = 0; j < TN; j++)
                    acc[i][j] += ar[i] * br[j];
        }

        if (kt + 1 < nk) {
            As[nxt][aCol+0][aRow] = a0.x; As[nxt][aCol+1][aRow] = a0.y;
            As[nxt][aCol+2][aRow] = a0.z; As[nxt][aCol+3][aRow] = a0.w;
            As[nxt][aCol+0][aRow+64] = a1.x; As[nxt][aCol+1][aRow+64] = a1.y;
            As[nxt][aCol+2][aRow+64] = a1.z; As[nxt][aCol+3][aRow+64] = a1.w;
            *(float4*)&Bs[nxt][bRow][bCol]     = b0;
            *(float4*)&Bs[nxt][bRow + 8][bCol] = b1;
        }
        __syncthreads();
    }

    // ---- epilogue: += bias, store ----
    #pragma unroll
    for (int i = 0; i < TM; i++) {
        const int r = blockRow + tr + i;
        if (r < M) {
            #pragma unroll
            for (int j = 0; j < TN; j += 4) {
                const int c = blockCol + tc + j;
                float4 o;
                o.x = acc[i][j + 0] + bias[c + 0];
                o.y = acc[i][j + 1] + bias[c + 1];
                o.z = acc[i][j + 2] + bias[c + 2];
                o.w = acc[i][j + 3] + bias[c + 3];
                *(float4*)(C + (size_t)r * N + c) = o;
            }
        }
    }
}

// =====================================================================
// Kernel 2: stable argsort of labels (counting sort; tiny, one thread)
// =====================================================================
__global__ void build_order_kernel(const int* __restrict__ labels)
{
    if (threadIdx.x == 0 && blockIdx.x == 0) {
        int start[N_WAY];
        int cnt[N_WAY];
        for (int c = 0; c < N_WAY; c++) cnt[c] = 0;
        for (int i = 0; i < N_SUPPORT; i++) cnt[labels[i]]++;
        int run = 0;
        for (int c = 0; c < N_WAY; c++) { start[c] = run; run += cnt[c]; }
        for (int i = 0; i < N_SUPPORT; i++) {
            int c = labels[i];
            g_order[start[c]++] = i;
        }
    }
}

// =====================================================================
// Kernel 3: prototypes. One block per class (128 blocks; >=100 write pad 0).
// Per dim: lower median (sorted[4]) + mean over K_SHOT=10, z = 0.5*(med+mean).
// Also reduces ||p||^2 and sum(p) per class.
// =====================================================================
__global__ __launch_bounds__(256)
void proto_kernel()
{
    const int c   = blockIdx.x;     // 0..127
    const int tid = threadIdx.x;
    __shared__ float s_sum[256], s_sum2[256];

    float psum = 0.f, psum2 = 0.f;

    if (c < N_WAY) {
        int idx[K_SHOT];
        #pragma unroll
        for (int j = 0; j < K_SHOT; j++) idx[j] = g_order[c * K_SHOT + j];

        for (int d = tid; d < D_EMB; d += 256) {
            float v[K_SHOT];
            #pragma unroll
            for (int j = 0; j < K_SHOT; j++)
                v[j] = g_Zs[(size_t)idx[j] * D_EMB + d];

            float mean = 0.f;
            #pragma unroll
            for (int j = 0; j < K_SHOT; j++) mean += v[j];
            mean *= (1.0f / K_SHOT);

            // fully-unrolled bubble sort (static indices -> stays in registers)
            #pragma unroll
            for (int p = 0; p < K_SHOT - 1; p++)
                #pragma unroll
                for (int q = 0; q < K_SHOT - 1 - p; q++) {
                    float lo = fminf(v[q], v[q + 1]);
                    float hi = fmaxf(v[q], v[q + 1]);
                    v[q] = lo; v[q + 1] = hi;
                }
            const float med = v[(K_SHOT - 1) / 2];   // lower median (torch semantics)
            const float zt  = 0.5f * (med + mean);

            g_proto[(size_t)c * D_EMB + d] = zt;
            psum  += zt;
            psum2 += zt * zt;
        }
    } else {
        for (int d = tid; d < D_EMB; d += 256)
            g_proto[(size_t)c * D_EMB + d] = 0.f;
    }

    s_sum[tid] = psum; s_sum2[tid] = psum2;
    __syncthreads();
    for (int s = 128; s > 0; s >>= 1) {
        if (tid < s) { s_sum[tid] += s_sum[tid + s]; s_sum2[tid] += s_sum2[tid + s]; }
        __syncthreads();
    }
    if (tid == 0 && c < N_WAY) { g_ps[c] = s_sum[0]; g_p2[c] = s_sum2[0]; }
}

// =====================================================================
// Kernel 4: per-query-row sum and sum-of-squares. One block per row.
// =====================================================================
__global__ __launch_bounds__(256)
void qstats_kernel()
{
    const int r   = blockIdx.x;
    const int tid = threadIdx.x;
    const float* z = g_Zq + (size_t)r * D_EMB;
    float s = 0.f, s2 = 0.f;
    #pragma unroll
    for (int d = tid; d < D_EMB; d += 256) {
        float v = z[d];
        s += v; s2 += v * v;
    }
    __shared__ float ss[256], ss2[256];
    ss[tid] = s; ss2[tid] = s2;
    __syncthreads();
    for (int st = 128; st > 0; st >>= 1) {
        if (tid < st) { ss[tid] += ss[tid + st]; ss2[tid] += ss2[tid + st]; }
        __syncthreads();
    }
    if (tid == 0) { g_qs[r] = ss[0]; g_q2[r] = ss2[0]; }
}

// =====================================================================
// Kernel 5: distance matrix. cross = Zq @ protoT, fused epilogue:
//   sq = q2 + p2 - 2*cross + 2*eps*(qs - ps) + D*eps^2 ; out = -sqrt(max(sq,0))
// Tile: 64 query rows x 128 proto cols (padded), K=1024, BK=16, 256 threads.
// =====================================================================
#define DBM 64
#define DBN 128
#define DBK 16
#define DTM 4
#define DTN 8

__global__ __launch_bounds__(256)
void dist_kernel(float* __restrict__ out)
{
    __shared__ float As2[DBK][DBM];   // As2[k][m]
    __shared__ float Bs2[DBK][DBN];   // Bs2[k][n] = proto[n][k]

    const int tid      = threadIdx.x;
    const int blockRow = blockIdx.x * DBM;

    // A tile: 64x16 = 256 float4, 1 per thread
    const int aRow = tid >> 2;            // 0..63
    const int aCol = (tid & 3) << 2;      // 0,4,8,12

    const int tr = (tid >> 4) * DTM;      // 0..60
    const int tc = (tid & 15) * DTN;      // 0..120

    float acc[DTM][DTN] = {};

    const int nk = D_EMB / DBK;           // 64
    for (int kt = 0; kt < nk; kt++) {
        const int kc = kt * DBK;

        // load A (Zq) transposed into smem
        {
            float4 a = *(const float4*)(g_Zq + (size_t)(blockRow + aRow) * D_EMB + kc + aCol);
            As2[aCol + 0][aRow] = a.x; As2[aCol + 1][aRow] = a.y;
            As2[aCol + 2][aRow] = a.z; As2[aCol + 3][aRow] = a.w;
        }
        // load proto^T: 128 n x 16 k = 512 float4, 2 per thread
        #pragma unroll
        for (int s = 0; s < 2; s++) {
            const int idx = tid + s * 256;     // 0..511
            const int n   = idx >> 2;          // 0..127
            const int k4  = (idx & 3) << 2;    // 0,4,8,12
            float4 p = *(const float4*)(g_proto + (size_t)n * D_EMB + kc + k4);
            Bs2[k4 + 0][n] = p.x; Bs2[k4 + 1][n] = p.y;
            Bs2[k4 + 2][n] = p.z; Bs2[k4 + 3][n] = p.w;
        }
        __syncthreads();

        #pragma unroll
        for (int k = 0; k < DBK; k++) {
            float ar[DTM], br[DTN];
            *(float4*)&ar[0] = *(const float4*)&As2[k][tr];
            *(float4*)&br[0] = *(const float4*)&Bs2[k][tc];
            *(float4*)&br[4] = *(const float4*)&Bs2[k][tc + 4];
            #pragma unroll
            for (int i = 0; i < DTM; i++)
                #pragma unroll
                for (int j = 0; j < DTN; j++)
                    acc[i][j] += ar[i] * br[j];
        }
        __syncthreads();
    }

    const float deps2 = (float)D_EMB * EPS_F * EPS_F;
    #pragma unroll
    for (int i = 0; i < DTM; i++) {
        const int r = blockRow + tr + i;
        const float q2v = g_q2[r];
        const float qsv = g_qs[r];
        #pragma unroll
        for (int j = 0; j < DTN; j++) {
            const int c = tc + j;
            if (c < N_WAY) {
                float sq = q2v + g_p2[c] - 2.0f * acc[i][j]
                         + 2.0f * EPS_F * (qsv - g_ps[c]) + deps2;
                out[(size_t)r * N_WAY + c] = -sqrtf(fmaxf(sq, 0.0f));
            }
        }
    }
}

// =====================================================================
// launch
// =====================================================================
extern "C" void kernel_launch(void* const* d_in, const int* in_sizes, int n_in,
                              void* d_out, int out_size)
{
    const float* support = (const float*)d_in[0];   // [1000, 4096]
    const int*   labels  = (const int*)  d_in[1];   // [1000]
    const float* query   = (const float*)d_in[2];   // [8192, 4096]
    const float* W       = (const float*)d_in[3];   // [4096, 1024]
    const float* b       = (const float*)d_in[4];   // [1024]
    float*       out     = (float*)d_out;           // [8192, 100]

    // embeddings
    sgemm_bias_kernel<<<dim3(D_EMB / BN, (N_SUPPORT + BM - 1) / BM), 256>>>(support, W, b, 0, N_SUPPORT);
    sgemm_bias_kernel<<<dim3(D_EMB / BN, N_QUERY / BM), 256>>>(query, W, b, 1, N_QUERY);

    // prototypes
    build_order_kernel<<<1, 32>>>(labels);
    proto_kernel<<<128, 256>>>();

    // query row stats
    qstats_kernel<<<N_QUERY, 256>>>();

    // distances
    dist_kernel<<<N_QUERY / DBM, 256>>>(out);
}

// round 3
// speedup vs baseline: 2.7663x; 2.7663x over previous
#include <cuda_runtime.h>
#include <cuda_bf16.h>
#include <math.h>
#include <stdint.h>

#define N_WAY     100
#define K_SHOT    10
#define N_SUPPORT 1000
#define N_QUERY   8192
#define F_IN      4096
#define D_EMB     1024
#define EPS_F     1e-6f

#define M_TOT     9216   // 8192 query rows + 1000 support + 24 pad

// ---------------- scratch (static device globals; no allocations) ----------
__device__ __nv_bfloat16 g_Ahi[(size_t)M_TOT * F_IN];   // 75.5 MB
__device__ __nv_bfloat16 g_Alo[(size_t)M_TOT * F_IN];   // 75.5 MB
__device__ __nv_bfloat16 g_Wthi[(size_t)D_EMB * F_IN];  // 8 MB (W transposed)
__device__ __nv_bfloat16 g_Wtlo[(size_t)D_EMB * F_IN];  // 8 MB
__device__ float g_Z[(size_t)M_TOT * D_EMB];            // 37.7 MB embeddings
__device__ float g_proto[128 * D_EMB];
__device__ float g_p2[128];
__device__ float g_ps[128];
__device__ float g_q2[N_QUERY];
__device__ float g_qs[N_QUERY];
__device__ int   g_order[N_SUPPORT];

// ======================= portable PTX helpers ==============================
__device__ __forceinline__ uint32_t smem_u32(const void* p) {
    uint32_t a;
    asm("{ .reg .u64 t; cvta.to.shared.u64 t, %1; cvt.u32.u64 %0, t; }"
        : "=r"(a) : "l"(p));
    return a;
}
__device__ __forceinline__ void cp_async16(uint32_t dst, const void* src) {
    asm volatile("cp.async.cg.shared.global [%0], [%1], 16;"
                 :: "r"(dst), "l"(src) : "memory");
}
__device__ __forceinline__ void cp_commit() {
    asm volatile("cp.async.commit_group;" ::: "memory");
}
__device__ __forceinline__ void cp_wait1() {
    asm volatile("cp.async.wait_group 1;" ::: "memory");
}
__device__ __forceinline__ void cp_wait0() {
    asm volatile("cp.async.wait_group 0;" ::: "memory");
}
__device__ __forceinline__ void ldmx4(uint32_t* r, uint32_t addr) {
    asm volatile("ldmatrix.sync.aligned.m8n8.x4.shared.b16 {%0,%1,%2,%3}, [%4];"
                 : "=r"(r[0]), "=r"(r[1]), "=r"(r[2]), "=r"(r[3]) : "r"(addr));
}
__device__ __forceinline__ void mma_bf16(float* c, const uint32_t* a, const uint32_t* b) {
    asm volatile(
        "mma.sync.aligned.m16n8k16.row.col.f32.bf16.bf16.f32 "
        "{%0,%1,%2,%3}, {%4,%5,%6,%7}, {%8,%9}, {%0,%1,%2,%3};"
        : "+f"(c[0]), "+f"(c[1]), "+f"(c[2]), "+f"(c[3])
        : "r"(a[0]), "r"(a[1]), "r"(a[2]), "r"(a[3]), "r"(b[0]), "r"(b[1]));
}

// =====================================================================
// Kernel A: split fp32 inputs into bf16 hi/lo. Rows 0..8191 = query,
// 8192..9191 = support, 9192..9215 = zero pad.
// =====================================================================
__global__ void convert_A(const float* __restrict__ q, const float* __restrict__ s)
{
    size_t i = (size_t)blockIdx.x * blockDim.x + threadIdx.x;  // 4 elems each
    const size_t total = (size_t)M_TOT * F_IN / 4;
    if (i >= total) return;
    const size_t row = i / (F_IN / 4);
    const size_t seg = i % (F_IN / 4);
    float4 v;
    if (row < N_QUERY)                  v = *(const float4*)(q + row * F_IN + seg * 4);
    else if (row < N_QUERY + N_SUPPORT) v = *(const float4*)(s + (row - N_QUERY) * F_IN + seg * 4);
    else                                v = make_float4(0.f, 0.f, 0.f, 0.f);

    float x[4] = {v.x, v.y, v.z, v.w};
    union B4 { __nv_bfloat16 b[4]; uint2 u; } uh, ul;
    #pragma unroll
    for (int j = 0; j < 4; j++) {
        __nv_bfloat16 h = __float2bfloat16_rn(x[j]);
        uh.b[j] = h;
        ul.b[j] = __float2bfloat16_rn(x[j] - __bfloat162float(h));
    }
    *(uint2*)(g_Ahi + i * 4) = uh.u;
    *(uint2*)(g_Alo + i * 4) = ul.u;
}

// =====================================================================
// Kernel B: transpose W [4096,1024] -> Wt hi/lo [1024,4096] bf16
// =====================================================================
__global__ void convert_W(const float* __restrict__ W)
{
    __shared__ __nv_bfloat16 th[32][33];
    __shared__ __nv_bfloat16 tl[32][33];
    const int k0 = blockIdx.x * 32, n0 = blockIdx.y * 32;
    const int tx = threadIdx.x, ty = threadIdx.y;   // (32, 8)
    #pragma unroll
    for (int i = 0; i < 4; i++) {
        const int kk = ty + i * 8;
        float x = W[(size_t)(k0 + kk) * D_EMB + n0 + tx];
        __nv_bfloat16 h = __float2bfloat16_rn(x);
        th[kk][tx] = h;
        tl[kk][tx] = __float2bfloat16_rn(x - __bfloat162float(h));
    }
    __syncthreads();
    #pragma unroll
    for (int i = 0; i < 4; i++) {
        const int nn = ty + i * 8;
        g_Wthi[(size_t)(n0 + nn) * F_IN + k0 + tx] = th[tx][nn];
        g_Wtlo[(size_t)(n0 + nn) * F_IN + k0 + tx] = tl[tx][nn];
    }
}

// =====================================================================
// Kernel C: bf16x3 tensor-core GEMM via mma.sync (sm_100 portable).
//   g_Z[M_TOT,1024] = (Ahi+Alo) @ (Whi+Wlo)^T + bias   (hi*hi+hi*lo+lo*hi)
// CTA 128x256, BK=32, 8 warps (2m x 4n), warp tile 64x64.
// SMEM rows strided 80B -> ldmatrix conflict-free. cp.async double buffer.
// =====================================================================
#define GM 128
#define GN 256
#define GK 32
#define NCH (F_IN / GK)          // 128
#define ROWB 80                  // bytes per smem row (32 bf16 + 8 pad)
#define SA_HI 0
#define SA_LO (GM * ROWB)                 // 10240
#define SB_HI (2 * GM * ROWB)             // 20480
#define SB_LO (2 * GM * ROWB + GN * ROWB) // 40960
#define STAGE (2 * GM * ROWB + 2 * GN * ROWB)  // 61440
#define GEMM_SMEM (2 * STAGE)                  // 122880

__device__ __forceinline__ void copy_chunk(uint32_t sb, int blockRow, int blockCol,
                                           int c, int tid)
{
    const size_t kc = (size_t)c * GK;
    // A: 128 rows x 4 segs x {hi,lo} = 1024 x 16B
    #pragma unroll
    for (int i = 0; i < 4; i++) {
        const int id  = tid + i * 256;
        const int arr = id >> 9;            // 0 hi, 1 lo
        const int rid = (id >> 2) & 127;
        const int seg = id & 3;
        const char* src = (const char*)(arr ? g_Alo : g_Ahi)
                        + ((size_t)(blockRow + rid) * F_IN + kc) * 2 + seg * 16;
        cp_async16(sb + arr * (GM * ROWB) + rid * ROWB + seg * 16, src);
    }
    // B: 256 rows x 4 segs x {hi,lo} = 2048 x 16B
    #pragma unroll
    for (int i = 0; i < 8; i++) {
        const int id  = tid + i * 256;
        const int arr = id >> 10;
        const int rid = (id >> 2) & 255;
        const int seg = id & 3;
        const char* src = (const char*)(arr ? g_Wtlo : g_Wthi)
                        + ((size_t)(blockCol + rid) * F_IN + kc) * 2 + seg * 16;
        cp_async16(sb + SB_HI + arr * (GN * ROWB) + rid * ROWB + seg * 16, src);
    }
}

__global__ __launch_bounds__(256, 1)
void gemm_bf16x3(const float* __restrict__ bias)
{
    extern __shared__ char smem[];
    const uint32_t sbase = smem_u32(smem);
    const int tid = threadIdx.x;
    const int wid = tid >> 5;
    const int l   = tid & 31;
    const int warpM = wid >> 2;         // 0..1 -> 64 rows
    const int warpN = wid & 3;          // 0..3 -> 64 cols
    const int blockRow = blockIdx.y * GM;
    const int blockCol = blockIdx.x * GN;

    // per-lane ldmatrix base offsets (within a stage)
    // A tile (m16 x k16), x4: lane l -> row l&15, k-block l>>4
    const uint32_t aOff = (uint32_t)((warpM * 64 + (l & 15)) * ROWB + (l >> 4) * 16);
    // B pair of n8 tiles (n16 x k16), x4: lane l -> n = (l&7) + ((l>>4)&1)*8, k-block (l>>3)&1
    uint32_t bOff[4];
    #pragma unroll
    for (int p = 0; p < 4; p++)
        bOff[p] = (uint32_t)(SB_HI + (warpN * 64 + p * 16 + ((l >> 4) & 1) * 8 + (l & 7)) * ROWB
                             + ((l >> 3) & 1) * 16);

    float acc[4][8][4];
    #pragma unroll
    for (int mt = 0; mt < 4; mt++)
        #pragma unroll
        for (int nt = 0; nt < 8; nt++)
            #pragma unroll
            for (int r = 0; r < 4; r++) acc[mt][nt][r] = 0.f;

    // prologue
    copy_chunk(sbase, blockRow, blockCol, 0, tid);
    cp_commit();

    for (int c = 0; c < NCH; c++) {
        const uint32_t cur = (uint32_t)(c & 1);
        if (c + 1 < NCH) {
            copy_chunk(sbase + (cur ^ 1) * STAGE, blockRow, blockCol, c + 1, tid);
            cp_commit();
            cp_wait1();
        } else {
            cp_wait0();
        }
        __syncthreads();

        const uint32_t st = sbase + cur * STAGE;
        #pragma unroll
        for (int ks = 0; ks < 2; ks++) {
            const uint32_t kb = ks * 32;   // 16 bf16 = 32B
            uint32_t aH[4][4], bH[4][4], bL[4][4], aL[4][4];

            #pragma unroll
            for (int mt = 0; mt < 4; mt++) ldmx4(aH[mt], st + aOff + mt * (16 * ROWB) + kb);
            #pragma unroll
            for (int p = 0; p < 4; p++)   ldmx4(bH[p], st + bOff[p] + kb);

            #pragma unroll
            for (int mt = 0; mt < 4; mt++)
                #pragma unroll
                for (int p = 0; p < 4; p++) {
                    mma_bf16(acc[mt][p * 2 + 0], aH[mt], &bH[p][0]);
                    mma_bf16(acc[mt][p * 2 + 1], aH[mt], &bH[p][2]);
                }

            #pragma unroll
            for (int p = 0; p < 4; p++)   ldmx4(bL[p], st + bOff[p] + (GN * ROWB) + kb);
            #pragma unroll
            for (int mt = 0; mt < 4; mt++)
                #pragma unroll
                for (int p = 0; p < 4; p++) {
                    mma_bf16(acc[mt][p * 2 + 0], aH[mt], &bL[p][0]);
                    mma_bf16(acc[mt][p * 2 + 1], aH[mt], &bL[p][2]);
                }

            #pragma unroll
            for (int mt = 0; mt < 4; mt++) ldmx4(aL[mt], st + aOff + SA_LO + mt * (16 * ROWB) + kb);
            #pragma unroll
            for (int mt = 0; mt < 4; mt++)
                #pragma unroll
                for (int p = 0; p < 4; p++) {
                    mma_bf16(acc[mt][p * 2 + 0], aL[mt], &bH[p][0]);
                    mma_bf16(acc[mt][p * 2 + 1], aL[mt], &bH[p][2]);
                }
        }
        __syncthreads();
    }

    // epilogue: + bias, store fp32
    #pragma unroll
    for (int mt = 0; mt < 4; mt++) {
        const int r0 = blockRow + warpM * 64 + mt * 16 + (l >> 2);
        #pragma unroll
        for (int nt = 0; nt < 8; nt++) {
            const int col = blockCol + warpN * 64 + nt * 8 + (l & 3) * 2;
            const float b0 = bias[col], b1 = bias[col + 1];
            float2 v0 = make_float2(acc[mt][nt][0] + b0, acc[mt][nt][1] + b1);
            float2 v1 = make_float2(acc[mt][nt][2] + b0, acc[mt][nt][3] + b1);
            *(float2*)(g_Z + (size_t)r0 * D_EMB + col)       = v0;
            *(float2*)(g_Z + (size_t)(r0 + 8) * D_EMB + col) = v1;
        }
    }
}

// =====================================================================
// Kernel D: stable counting sort of labels
// =====================================================================
__global__ void build_order_kernel(const int* __restrict__ labels)
{
    if (threadIdx.x == 0 && blockIdx.x == 0) {
        int start[N_WAY], cnt[N_WAY];
        for (int c = 0; c < N_WAY; c++) cnt[c] = 0;
        for (int i = 0; i < N_SUPPORT; i++) cnt[labels[i]]++;
        int run = 0;
        for (int c = 0; c < N_WAY; c++) { start[c] = run; run += cnt[c]; }
        for (int i = 0; i < N_SUPPORT; i++) g_order[start[labels[i]]++] = i;
    }
}

// =====================================================================
// Kernel E: prototypes (lower median + mean), class stats
// =====================================================================
__global__ __launch_bounds__(256)
void proto_kernel()
{
    const int c   = blockIdx.x;
    const int tid = threadIdx.x;
    __shared__ float s_sum[256], s_sum2[256];

    float psum = 0.f, psum2 = 0.f;
    if (c < N_WAY) {
        int idx[K_SHOT];
        #pragma unroll
        for (int j = 0; j < K_SHOT; j++) idx[j] = g_order[c * K_SHOT + j];

        for (int d = tid; d < D_EMB; d += 256) {
            float v[K_SHOT];
            #pragma unroll
            for (int j = 0; j < K_SHOT; j++)
                v[j] = g_Z[(size_t)(N_QUERY + idx[j]) * D_EMB + d];

            float mean = 0.f;
            #pragma unroll
            for (int j = 0; j < K_SHOT; j++) mean += v[j];
            mean *= (1.0f / K_SHOT);

            #pragma unroll
            for (int p = 0; p < K_SHOT - 1; p++)
                #pragma unroll
                for (int q = 0; q < K_SHOT - 1 - p; q++) {
                    float lo = fminf(v[q], v[q + 1]);
                    float hi = fmaxf(v[q], v[q + 1]);
                    v[q] = lo; v[q + 1] = hi;
                }
            const float med = v[(K_SHOT - 1) / 2];
            const float zt  = 0.5f * (med + mean);
            g_proto[(size_t)c * D_EMB + d] = zt;
            psum += zt; psum2 += zt * zt;
        }
    } else {
        for (int d = tid; d < D_EMB; d += 256)
            g_proto[(size_t)c * D_EMB + d] = 0.f;
    }

    s_sum[tid] = psum; s_sum2[tid] = psum2;
    __syncthreads();
    for (int s = 128; s > 0; s >>= 1) {
        if (tid < s) { s_sum[tid] += s_sum[tid + s]; s_sum2[tid] += s_sum2[tid + s]; }
        __syncthreads();
    }
    if (tid == 0 && c < N_WAY) { g_ps[c] = s_sum[0]; g_p2[c] = s_sum2[0]; }
}

// =====================================================================
// Kernel F: per-query-row sum / sum-of-squares
// =====================================================================
__global__ __launch_bounds__(256)
void qstats_kernel()
{
    const int r   = blockIdx.x;
    const int tid = threadIdx.x;
    const float* z = g_Z + (size_t)r * D_EMB;
    float s = 0.f, s2 = 0.f;
    #pragma unroll
    for (int d = tid; d < D_EMB; d += 256) {
        float v = z[d];
        s += v; s2 += v * v;
    }
    __shared__ float ss[256], ss2[256];
    ss[tid] = s; ss2[tid] = s2;
    __syncthreads();
    for (int st = 128; st > 0; st >>= 1) {
        if (tid < st) { ss[tid] += ss[tid + st]; ss2[tid] += ss2[tid + st]; }
        __syncthreads();
    }
    if (tid == 0) { g_qs[r] = ss[0]; g_q2[r] = ss2[0]; }
}

// =====================================================================
// Kernel G: distance matrix with fused PairwiseDistance-eps epilogue
// =====================================================================
#define DBM 64
#define DBN 128
#define DBK 16
#define DTM 4
#define DTN 8

__global__ __launch_bounds__(256)
void dist_kernel(float* __restrict__ out)
{
    __shared__ float As2[DBK][DBM];
    __shared__ float Bs2[DBK][DBN];

    const int tid      = threadIdx.x;
    const int blockRow = blockIdx.x * DBM;

    const int aRow = tid >> 2;
    const int aCol = (tid & 3) << 2;
    const int tr = (tid >> 4) * DTM;
    const int tc = (tid & 15) * DTN;

    float acc[DTM][DTN] = {};

    const int nk = D_EMB / DBK;
    for (int kt = 0; kt < nk; kt++) {
        const int kc = kt * DBK;
        {
            float4 a = *(const float4*)(g_Z + (size_t)(blockRow + aRow) * D_EMB + kc + aCol);
            As2[aCol + 0][aRow] = a.x; As2[aCol + 1][aRow] = a.y;
            As2[aCol + 2][aRow] = a.z; As2[aCol + 3][aRow] = a.w;
        }
        #pragma unroll
        for (int s = 0; s < 2; s++) {
            const int idx = tid + s * 256;
            const int n   = idx >> 2;
            const int k4  = (idx & 3) << 2;
            float4 p = *(const float4*)(g_proto + (size_t)n * D_EMB + kc + k4);
            Bs2[k4 + 0][n] = p.x; Bs2[k4 + 1][n] = p.y;
            Bs2[k4 + 2][n] = p.z; Bs2[k4 + 3][n] = p.w;
        }
        __syncthreads();

        #pragma unroll
        for (int k = 0; k < DBK; k++) {
            float ar[DTM], br[DTN];
            *(float4*)&ar[0] = *(const float4*)&As2[k][tr];
            *(float4*)&br[0] = *(const float4*)&Bs2[k][tc];
            *(float4*)&br[4] = *(const float4*)&Bs2[k][tc + 4];
            #pragma unroll
            for (int i = 0; i < DTM; i++)
                #pragma unroll
                for (int j = 0; j < DTN; j++)
                    acc[i][j] += ar[i] * br[j];
        }
        __syncthreads();
    }

    const float deps2 = (float)D_EMB * EPS_F * EPS_F;
    #pragma unroll
    for (int i = 0; i < DTM; i++) {
        const int r = blockRow + tr + i;
        const float q2v = g_q2[r];
        const float qsv = g_qs[r];
        #pragma unroll
        for (int j = 0; j < DTN; j++) {
            const int c = tc + j;
            if (c < N_WAY) {
                float sq = q2v + g_p2[c] - 2.0f * acc[i][j]
                         + 2.0f * EPS_F * (qsv - g_ps[c]) + deps2;
                out[(size_t)r * N_WAY + c] = -sqrtf(fmaxf(sq, 0.0f));
            }
        }
    }
}

// =====================================================================
// launch
// =====================================================================
extern "C" void kernel_launch(void* const* d_in, const int* in_sizes, int n_in,
                              void* d_out, int out_size)
{
    const float* support = (const float*)d_in[0];   // [1000, 4096]
    const int*   labels  = (const int*)  d_in[1];   // [1000]
    const float* query   = (const float*)d_in[2];   // [8192, 4096]
    const float* W       = (const float*)d_in[3];   // [4096, 1024]
    const float* b       = (const float*)d_in[4];   // [1024]
    float*       out     = (float*)d_out;           // [8192, 100]

    cudaFuncSetAttribute(gemm_bf16x3,
                         cudaFuncAttributeMaxDynamicSharedMemorySize, GEMM_SMEM);

    // 1. fp32 -> bf16 hi/lo splits
    {
        const size_t total = (size_t)M_TOT * F_IN / 4;
        convert_A<<<(unsigned)((total + 255) / 256), 256>>>(query, support);
    }
    convert_W<<<dim3(F_IN / 32, D_EMB / 32), dim3(32, 8)>>>(W);

    // 2. tensor-core GEMM (query + support fused): grid 4 x 72
    gemm_bf16x3<<<dim3(D_EMB / GN, M_TOT / GM), 256, GEMM_SMEM>>>(b);

    // 3. prototypes
    build_order_kernel<<<1, 32>>>(labels);
    proto_kernel<<<128, 256>>>();

    // 4. query row stats
    qstats_kernel<<<N_QUERY, 256>>>();

    // 5. distances
    dist_kernel<<<N_QUERY / DBM, 256>>>(out);
}

// round 4
// speedup vs baseline: 3.3843x; 1.2234x over previous
#include <cuda_runtime.h>
#include <cuda_bf16.h>
#include <math.h>
#include <stdint.h>

#define N_WAY     100
#define K_SHOT    10
#define N_SUPPORT 1000
#define N_QUERY   8192
#define F_IN      4096
#define D_EMB     1024
#define EPS_F     1e-6f

#define M_TOT     9216   // 8192 query rows + 1000 support + 24 pad

// ---------------- scratch (static device globals; no allocations) ----------
__device__ __nv_bfloat16 g_Ahi[(size_t)M_TOT * F_IN];
__device__ __nv_bfloat16 g_Alo[(size_t)M_TOT * F_IN];
__device__ __nv_bfloat16 g_Wthi[(size_t)D_EMB * F_IN];
__device__ __nv_bfloat16 g_Wtlo[(size_t)D_EMB * F_IN];
__device__ float g_Z[(size_t)M_TOT * D_EMB];
__device__ float g_proto[128 * D_EMB];
__device__ float g_p2[128];
__device__ float g_ps[128];
__device__ float g_q2[N_QUERY];
__device__ float g_qs[N_QUERY];
__device__ int   g_order[N_SUPPORT];

// ======================= portable PTX helpers ==============================
__device__ __forceinline__ uint32_t smem_u32(const void* p) {
    uint32_t a;
    asm("{ .reg .u64 t; cvta.to.shared.u64 t, %1; cvt.u32.u64 %0, t; }"
        : "=r"(a) : "l"(p));
    return a;
}
__device__ __forceinline__ void cp_async16(uint32_t dst, const void* src) {
    asm volatile("cp.async.cg.shared.global [%0], [%1], 16;"
                 :: "r"(dst), "l"(src) : "memory");
}
__device__ __forceinline__ void cp_commit() {
    asm volatile("cp.async.commit_group;" ::: "memory");
}
__device__ __forceinline__ void cp_wait1() {
    asm volatile("cp.async.wait_group 1;" ::: "memory");
}
__device__ __forceinline__ void ldmx4(uint32_t* r, uint32_t addr) {
    asm volatile("ldmatrix.sync.aligned.m8n8.x4.shared.b16 {%0,%1,%2,%3}, [%4];"
                 : "=r"(r[0]), "=r"(r[1]), "=r"(r[2]), "=r"(r[3]) : "r"(addr));
}
__device__ __forceinline__ void mma_bf16(float* c, const uint32_t* a, const uint32_t* b) {
    asm volatile(
        "mma.sync.aligned.m16n8k16.row.col.f32.bf16.bf16.f32 "
        "{%0,%1,%2,%3}, {%4,%5,%6,%7}, {%8,%9}, {%0,%1,%2,%3};"
        : "+f"(c[0]), "+f"(c[1]), "+f"(c[2]), "+f"(c[3])
        : "r"(a[0]), "r"(a[1]), "r"(a[2]), "r"(a[3]), "r"(b[0]), "r"(b[1]));
}

// =====================================================================
// Kernel A: split fp32 inputs into bf16 hi/lo
// =====================================================================
__global__ void convert_A(const float* __restrict__ q, const float* __restrict__ s)
{
    size_t i = (size_t)blockIdx.x * blockDim.x + threadIdx.x;
    const size_t total = (size_t)M_TOT * F_IN / 4;
    if (i >= total) return;
    const size_t row = i / (F_IN / 4);
    const size_t seg = i % (F_IN / 4);
    float4 v;
    if (row < N_QUERY)                  v = *(const float4*)(q + row * F_IN + seg * 4);
    else if (row < N_QUERY + N_SUPPORT) v = *(const float4*)(s + (row - N_QUERY) * F_IN + seg * 4);
    else                                v = make_float4(0.f, 0.f, 0.f, 0.f);

    float x[4] = {v.x, v.y, v.z, v.w};
    union B4 { __nv_bfloat16 b[4]; uint2 u; } uh, ul;
    #pragma unroll
    for (int j = 0; j < 4; j++) {
        __nv_bfloat16 h = __float2bfloat16_rn(x[j]);
        uh.b[j] = h;
        ul.b[j] = __float2bfloat16_rn(x[j] - __bfloat162float(h));
    }
    *(uint2*)(g_Ahi + i * 4) = uh.u;
    *(uint2*)(g_Alo + i * 4) = ul.u;
}

// =====================================================================
// Kernel B: transpose W [4096,1024] -> Wt hi/lo [1024,4096] bf16
// =====================================================================
__global__ void convert_W(const float* __restrict__ W)
{
    __shared__ __nv_bfloat16 th[32][33];
    __shared__ __nv_bfloat16 tl[32][33];
    const int k0 = blockIdx.x * 32, n0 = blockIdx.y * 32;
    const int tx = threadIdx.x, ty = threadIdx.y;   // (32, 8)
    #pragma unroll
    for (int i = 0; i < 4; i++) {
        const int kk = ty + i * 8;
        float x = W[(size_t)(k0 + kk) * D_EMB + n0 + tx];
        __nv_bfloat16 h = __float2bfloat16_rn(x);
        th[kk][tx] = h;
        tl[kk][tx] = __float2bfloat16_rn(x - __bfloat162float(h));
    }
    __syncthreads();
    #pragma unroll
    for (int i = 0; i < 4; i++) {
        const int nn = ty + i * 8;
        g_Wthi[(size_t)(n0 + nn) * F_IN + k0 + tx] = th[tx][nn];
        g_Wtlo[(size_t)(n0 + nn) * F_IN + k0 + tx] = tl[tx][nn];
    }
}

// =====================================================================
// Kernel C: bf16x3 tensor-core GEMM, 3-stage cp.async multistage,
// single __syncthreads per main-loop iteration.
// =====================================================================
#define GM 128
#define GN 256
#define GK 32
#define NCH (F_IN / GK)          // 128
#define ROWB 80                  // 32 bf16 + 8 pad bytes
#define SA_HI 0
#define SA_LO (GM * ROWB)
#define SB_HI (2 * GM * ROWB)
#define SB_LO (2 * GM * ROWB + GN * ROWB)
#define STAGE (2 * GM * ROWB + 2 * GN * ROWB)  // 61440
#define NSTAGE 3
#define GEMM_SMEM (NSTAGE * STAGE)             // 184320

__device__ __forceinline__ void copy_chunk(uint32_t sb, int blockRow, int blockCol,
                                           int c, int tid)
{
    const size_t kc = (size_t)c * GK;
    #pragma unroll
    for (int i = 0; i < 4; i++) {
        const int id  = tid + i * 256;
        const int arr = id >> 9;
        const int rid = (id >> 2) & 127;
        const int seg = id & 3;
        const char* src = (const char*)(arr ? g_Alo : g_Ahi)
                        + ((size_t)(blockRow + rid) * F_IN + kc) * 2 + seg * 16;
        cp_async16(sb + arr * (GM * ROWB) + rid * ROWB + seg * 16, src);
    }
    #pragma unroll
    for (int i = 0; i < 8; i++) {
        const int id  = tid + i * 256;
        const int arr = id >> 10;
        const int rid = (id >> 2) & 255;
        const int seg = id & 3;
        const char* src = (const char*)(arr ? g_Wtlo : g_Wthi)
                        + ((size_t)(blockCol + rid) * F_IN + kc) * 2 + seg * 16;
        cp_async16(sb + SB_HI + arr * (GN * ROWB) + rid * ROWB + seg * 16, src);
    }
}

__global__ __launch_bounds__(256, 1)
void gemm_bf16x3(const float* __restrict__ bias)
{
    extern __shared__ char smem[];
    const uint32_t sbase = smem_u32(smem);
    const int tid = threadIdx.x;
    const int wid = tid >> 5;
    const int l   = tid & 31;
    const int warpM = wid >> 2;
    const int warpN = wid & 3;
    const int blockRow = blockIdx.y * GM;
    const int blockCol = blockIdx.x * GN;

    const uint32_t aOff = (uint32_t)((warpM * 64 + (l & 15)) * ROWB + (l >> 4) * 16);
    uint32_t bOff[4];
    #pragma unroll
    for (int p = 0; p < 4; p++)
        bOff[p] = (uint32_t)(SB_HI + (warpN * 64 + p * 16 + ((l >> 4) & 1) * 8 + (l & 7)) * ROWB
                             + ((l >> 3) & 1) * 16);

    float acc[4][8][4];
    #pragma unroll
    for (int mt = 0; mt < 4; mt++)
        #pragma unroll
        for (int nt = 0; nt < 8; nt++)
            #pragma unroll
            for (int r = 0; r < 4; r++) acc[mt][nt][r] = 0.f;

    // prologue: stages 0, 1
    copy_chunk(sbase, blockRow, blockCol, 0, tid);
    cp_commit();
    copy_chunk(sbase + STAGE, blockRow, blockCol, 1, tid);
    cp_commit();

    uint32_t stOff = 0;                       // stage offset of chunk c
    uint32_t wrOff = 2 * STAGE;               // stage offset of chunk c+2

    for (int c = 0; c < NCH; c++) {
        cp_wait1();                           // chunk c resident
        __syncthreads();                      // also protects stage about to be overwritten

        const uint32_t st = sbase + stOff;
        #pragma unroll
        for (int ks = 0; ks < 2; ks++) {
            const uint32_t kb = ks * 32;
            uint32_t aH[4][4], bH[4][4], bL[4][4], aL[4][4];

            #pragma unroll
            for (int mt = 0; mt < 4; mt++) ldmx4(aH[mt], st + aOff + mt * (16 * ROWB) + kb);
            #pragma unroll
            for (int p = 0; p < 4; p++)   ldmx4(bH[p], st + bOff[p] + kb);

            #pragma unroll
            for (int p = 0; p < 4; p++)   ldmx4(bL[p], st + bOff[p] + (GN * ROWB) + kb);
            #pragma unroll
            for (int mt = 0; mt < 4; mt++)
                #pragma unroll
                for (int p = 0; p < 4; p++) {
                    mma_bf16(acc[mt][p * 2 + 0], aH[mt], &bH[p][0]);
                    mma_bf16(acc[mt][p * 2 + 1], aH[mt], &bH[p][2]);
                }

            #pragma unroll
            for (int mt = 0; mt < 4; mt++) ldmx4(aL[mt], st + aOff + SA_LO + mt * (16 * ROWB) + kb);
            #pragma unroll
            for (int mt = 0; mt < 4; mt++)
                #pragma unroll
                for (int p = 0; p < 4; p++) {
                    mma_bf16(acc[mt][p * 2 + 0], aH[mt], &bL[p][0]);
                    mma_bf16(acc[mt][p * 2 + 1], aH[mt], &bL[p][2]);
                }

            #pragma unroll
            for (int mt = 0; mt < 4; mt++)
                #pragma unroll
                for (int p = 0; p < 4; p++) {
                    mma_bf16(acc[mt][p * 2 + 0], aL[mt], &bH[p][0]);
                    mma_bf16(acc[mt][p * 2 + 1], aL[mt], &bH[p][2]);
                }
        }

        if (c + 2 < NCH) {
            copy_chunk(sbase + wrOff, blockRow, blockCol, c + 2, tid);
        }
        cp_commit();   // commit even if empty to keep group accounting uniform

        stOff += STAGE; if (stOff == NSTAGE * STAGE) stOff = 0;
        wrOff += STAGE; if (wrOff == NSTAGE * STAGE) wrOff = 0;
    }

    // epilogue: + bias, store fp32
    #pragma unroll
    for (int mt = 0; mt < 4; mt++) {
        const int r0 = blockRow + warpM * 64 + mt * 16 + (l >> 2);
        #pragma unroll
        for (int nt = 0; nt < 8; nt++) {
            const int col = blockCol + warpN * 64 + nt * 8 + (l & 3) * 2;
            const float b0 = bias[col], b1 = bias[col + 1];
            float2 v0 = make_float2(acc[mt][nt][0] + b0, acc[mt][nt][1] + b1);
            float2 v1 = make_float2(acc[mt][nt][2] + b0, acc[mt][nt][3] + b1);
            *(float2*)(g_Z + (size_t)r0 * D_EMB + col)       = v0;
            *(float2*)(g_Z + (size_t)(r0 + 8) * D_EMB + col) = v1;
        }
    }
}

// =====================================================================
// Kernel D: stable order — warp per class, ballot compaction
// =====================================================================
__global__ void build_order_kernel(const int* __restrict__ labels)
{
    const int c = blockIdx.x;           // 0..99
    const int l = threadIdx.x;          // 0..31
    int base = 0;
    for (int i0 = 0; i0 < N_SUPPORT; i0 += 32) {
        const int i = i0 + l;
        const bool match = (i < N_SUPPORT) && (labels[i] == c);
        const unsigned m = __ballot_sync(0xFFFFFFFFu, match);
        if (match) {
            const int pos = base + __popc(m & ((1u << l) - 1u));
            if (pos < K_SHOT) g_order[c * K_SHOT + pos] = i;
        }
        base += __popc(m);
    }
}

// =====================================================================
// Kernel E: prototypes (lower median + mean), class stats
// =====================================================================
__global__ __launch_bounds__(256)
void proto_kernel()
{
    const int c   = blockIdx.x;
    const int tid = threadIdx.x;
    __shared__ float s_sum[256], s_sum2[256];

    float psum = 0.f, psum2 = 0.f;
    if (c < N_WAY) {
        int idx[K_SHOT];
        #pragma unroll
        for (int j = 0; j < K_SHOT; j++) idx[j] = g_order[c * K_SHOT + j];

        for (int d = tid; d < D_EMB; d += 256) {
            float v[K_SHOT];
            #pragma unroll
            for (int j = 0; j < K_SHOT; j++)
                v[j] = g_Z[(size_t)(N_QUERY + idx[j]) * D_EMB + d];

            float mean = 0.f;
            #pragma unroll
            for (int j = 0; j < K_SHOT; j++) mean += v[j];
            mean *= (1.0f / K_SHOT);

            #pragma unroll
            for (int p = 0; p < K_SHOT - 1; p++)
                #pragma unroll
                for (int q = 0; q < K_SHOT - 1 - p; q++) {
                    float lo = fminf(v[q], v[q + 1]);
                    float hi = fmaxf(v[q], v[q + 1]);
                    v[q] = lo; v[q + 1] = hi;
                }
            const float med = v[(K_SHOT - 1) / 2];
            const float zt  = 0.5f * (med + mean);
            g_proto[(size_t)c * D_EMB + d] = zt;
            psum += zt; psum2 += zt * zt;
        }
    } else {
        for (int d = tid; d < D_EMB; d += 256)
            g_proto[(size_t)c * D_EMB + d] = 0.f;
    }

    s_sum[tid] = psum; s_sum2[tid] = psum2;
    __syncthreads();
    for (int s = 128; s > 0; s >>= 1) {
        if (tid < s) { s_sum[tid] += s_sum[tid + s]; s_sum2[tid] += s_sum2[tid + s]; }
        __syncthreads();
    }
    if (tid == 0 && c < N_WAY) { g_ps[c] = s_sum[0]; g_p2[c] = s_sum2[0]; }
}

// =====================================================================
// Kernel F: per-query-row sum / sum-of-squares — warp per row
// =====================================================================
__global__ __launch_bounds__(256)
void qstats_kernel()
{
    const int warp = (blockIdx.x * blockDim.x + threadIdx.x) >> 5;
    const int l    = threadIdx.x & 31;
    if (warp >= N_QUERY) return;
    const float* z = g_Z + (size_t)warp * D_EMB;
    float s = 0.f, s2 = 0.f;
    #pragma unroll
    for (int i = 0; i < 8; i++) {
        float4 v = *(const float4*)(z + (l + i * 32) * 4);
        s  += v.x + v.y + v.z + v.w;
        s2 += v.x * v.x + v.y * v.y + v.z * v.z + v.w * v.w;
    }
    #pragma unroll
    for (int off = 16; off > 0; off >>= 1) {
        s  += __shfl_xor_sync(0xFFFFFFFFu, s,  off);
        s2 += __shfl_xor_sync(0xFFFFFFFFu, s2, off);
    }
    if (l == 0) { g_qs[warp] = s; g_q2[warp] = s2; }
}

// =====================================================================
// Kernel G: distance matrix with fused PairwiseDistance-eps epilogue
// =====================================================================
#define DBM 64
#define DBN 128
#define DBK 16
#define DTM 4
#define DTN 8

__global__ __launch_bounds__(256)
void dist_kernel(float* __restrict__ out)
{
    __shared__ float As2[DBK][DBM];
    __shared__ float Bs2[DBK][DBN];

    const int tid      = threadIdx.x;
    const int blockRow = blockIdx.x * DBM;

    const int aRow = tid >> 2;
    const int aCol = (tid & 3) << 2;
    const int tr = (tid >> 4) * DTM;
    const int tc = (tid & 15) * DTN;

    float acc[DTM][DTN] = {};

    const int nk = D_EMB / DBK;
    for (int kt = 0; kt < nk; kt++) {
        const int kc = kt * DBK;
        {
            float4 a = *(const float4*)(g_Z + (size_t)(blockRow + aRow) * D_EMB + kc + aCol);
            As2[aCol + 0][aRow] = a.x; As2[aCol + 1][aRow] = a.y;
            As2[aCol + 2][aRow] = a.z; As2[aCol + 3][aRow] = a.w;
        }
        #pragma unroll
        for (int s = 0; s < 2; s++) {
            const int idx = tid + s * 256;
            const int n   = idx >> 2;
            const int k4  = (idx & 3) << 2;
            float4 p = *(const float4*)(g_proto + (size_t)n * D_EMB + kc + k4);
            Bs2[k4 + 0][n] = p.x; Bs2[k4 + 1][n] = p.y;
            Bs2[k4 + 2][n] = p.z; Bs2[k4 + 3][n] = p.w;
        }
        __syncthreads();

        #pragma unroll
        for (int k = 0; k < DBK; k++) {
            float ar[DTM], br[DTN];
            *(float4*)&ar[0] = *(const float4*)&As2[k][tr];
            *(float4*)&br[0] = *(const float4*)&Bs2[k][tc];
            *(float4*)&br[4] = *(const float4*)&Bs2[k][tc + 4];
            #pragma unroll
            for (int i = 0; i < DTM; i++)
                #pragma unroll
                for (int j = 0; j < DTN; j++)
                    acc[i][j] += ar[i] * br[j];
        }
        __syncthreads();
    }

    const float deps2 = (float)D_EMB * EPS_F * EPS_F;
    #pragma unroll
    for (int i = 0; i < DTM; i++) {
        const int r = blockRow + tr + i;
        const float q2v = g_q2[r];
        const float qsv = g_qs[r];
        #pragma unroll
        for (int j = 0; j < DTN; j++) {
            const int c = tc + j;
            if (c < N_WAY) {
                float sq = q2v + g_p2[c] - 2.0f * acc[i][j]
                         + 2.0f * EPS_F * (qsv - g_ps[c]) + deps2;
                out[(size_t)r * N_WAY + c] = -sqrtf(fmaxf(sq, 0.0f));
            }
        }
    }
}

// =====================================================================
// launch
// =====================================================================
extern "C" void kernel_launch(void* const* d_in, const int* in_sizes, int n_in,
                              void* d_out, int out_size)
{
    const float* support = (const float*)d_in[0];
    const int*   labels  = (const int*)  d_in[1];
    const float* query   = (const float*)d_in[2];
    const float* W       = (const float*)d_in[3];
    const float* b       = (const float*)d_in[4];
    float*       out     = (float*)d_out;

    cudaFuncSetAttribute(gemm_bf16x3,
                         cudaFuncAttributeMaxDynamicSharedMemorySize, GEMM_SMEM);

    {
        const size_t total = (size_t)M_TOT * F_IN / 4;
        convert_A<<<(unsigned)((total + 255) / 256), 256>>>(query, support);
    }
    convert_W<<<dim3(F_IN / 32, D_EMB / 32), dim3(32, 8)>>>(W);

    gemm_bf16x3<<<dim3(D_EMB / GN, M_TOT / GM), 256, GEMM_SMEM>>>(b);

    build_order_kernel<<<N_WAY, 32>>>(labels);
    proto_kernel<<<128, 256>>>();
    qstats_kernel<<<N_QUERY / 8, 256>>>();
    dist_kernel<<<N_QUERY / DBM, 256>>>(out);
}